// round 2
// baseline (speedup 1.0000x reference)
#include <cuda_runtime.h>
#include <math.h>

#define NN    50000
#define NE    800000
#define ETOT  850000     // NE + NN self loops
#define H1    10
#define C1    36
#define D1    360        // H1*C1
#define D2    128
#define NG    128

// ---------------- device scratch (no mallocs allowed) ----------------
__device__ int   g_src[ETOT];
__device__ int   g_dst[ETOT];
__device__ int   g_deg[NN];
__device__ int   g_rowstart[NN];
__device__ int   g_cursor[NN];
__device__ int   g_order[ETOT];

__device__ float g_h1pre[(size_t)NN * D1];   // 72 MB
__device__ float g_als1[NN * H1];
__device__ float g_ald1[NN * H1];
__device__ float g_p1[(size_t)ETOT * H1];    // 34 MB
__device__ float g_s1[NN * H1];
__device__ float g_h1act[(size_t)NN * D1];   // 72 MB
__device__ float g_h2pre[(size_t)NN * D2];   // 25.6 MB
__device__ float g_als2[NN];
__device__ float g_ald2[NN];
__device__ float g_p2[ETOT];
__device__ float g_s2[NN];
__device__ float g_h2act[(size_t)NN * D2];   // 25.6 MB
__device__ float g_pool[NG * D2];

// ---------------- init / CSR build ----------------
__global__ void init_kernel() {
    int i = blockIdx.x * blockDim.x + threadIdx.x;
    int stride = gridDim.x * blockDim.x;
    for (int j = i; j < NN * H1; j += stride) g_s1[j] = 0.f;
    for (int j = i; j < NN; j += stride) {
        g_s2[j] = 0.f; g_deg[j] = 0; g_cursor[j] = 0;
    }
    for (int j = i; j < NG * D2; j += stride)
        g_pool[j] = __int_as_float(0xFF800000); // -inf
}

__global__ void convert_kernel(const int* __restrict__ ei) {
    int i = blockIdx.x * blockDim.x + threadIdx.x;
    if (i >= ETOT) return;
    int s, d;
    if (i < NE) {
        s = ei[i]; d = ei[NE + i];
        // defensive clamp: invalid data should fail validation, not crash
        s = min(max(s, 0), NN - 1);
        d = min(max(d, 0), NN - 1);
    } else {
        s = d = i - NE;                      // self loop
    }
    g_src[i] = s; g_dst[i] = d;
    atomicAdd(&g_deg[d], 1);
}

__global__ void scan_kernel() {          // exclusive scan of g_deg -> g_rowstart
    __shared__ int tmp[1024];
    __shared__ int carry_s;
    int t = threadIdx.x;
    if (t == 0) carry_s = 0;
    __syncthreads();
    for (int base = 0; base < NN; base += 1024) {
        int i = base + t;
        int v = (i < NN) ? g_deg[i] : 0;
        tmp[t] = v;
        __syncthreads();
        for (int off = 1; off < 1024; off <<= 1) {
            int add = (t >= off) ? tmp[t - off] : 0;
            __syncthreads();
            tmp[t] += add;
            __syncthreads();
        }
        int carry = carry_s;
        if (i < NN) g_rowstart[i] = carry + tmp[t] - v;
        __syncthreads();
        if (t == 1023) carry_s = carry + tmp[1023];
        __syncthreads();
    }
}

__global__ void scatter_kernel() {
    int i = blockIdx.x * blockDim.x + threadIdx.x;
    if (i >= ETOT) return;
    int d = g_dst[i];
    int pos = atomicAdd(&g_cursor[d], 1);
    g_order[g_rowstart[d] + pos] = i;
}

// ---------------- layer 1: h1 = x@W1, attention coefficients ----------------
__global__ void mm1_kernel(const float* __restrict__ x,
                           const float* __restrict__ W1,
                           const float* __restrict__ asrc,
                           const float* __restrict__ adst) {
    // 8 nodes per block, 384 threads (360 active for features)
    int n0 = blockIdx.x * 8;
    int t = threadIdx.x;
    __shared__ float xs[8 * C1];      // 288
    __shared__ float hs[8 * D1];      // 11.5 KB
    if (t < 8 * C1) xs[t] = x[(size_t)n0 * C1 + t];
    __syncthreads();
    if (t < D1) {
        float acc[8];
#pragma unroll
        for (int n = 0; n < 8; n++) acc[n] = 0.f;
        for (int k = 0; k < C1; k++) {
            float w = W1[k * D1 + t];
#pragma unroll
            for (int n = 0; n < 8; n++) acc[n] = fmaf(xs[n * C1 + k], w, acc[n]);
        }
#pragma unroll
        for (int n = 0; n < 8; n++) {
            g_h1pre[(size_t)(n0 + n) * D1 + t] = acc[n];
            hs[n * D1 + t] = acc[n];
        }
    }
    __syncthreads();
    if (t < 160) {   // 8 nodes * 10 heads * {src,dst}
        int n = t / 20, r = t % 20, h = r >> 1, sd = r & 1;
        const float* a = sd ? adst : asrc;
        float s = 0.f;
        for (int c = 0; c < C1; c++)
            s = fmaf(hs[n * D1 + h * C1 + c], a[h * C1 + c], s);
        if (sd) g_ald1[(n0 + n) * H1 + h] = s;
        else    g_als1[(n0 + n) * H1 + h] = s;
    }
}

// edge pass: p = exp(leaky_relu(als[src]+ald[dst])), s[dst] += p
__global__ void e1_kernel() {
    int idx = blockIdx.x * blockDim.x + threadIdx.x;
    if (idx >= ETOT * H1) return;
    int eid = idx / H1, h = idx % H1;
    int s = g_src[eid], d = g_dst[eid];
    float e = g_als1[s * H1 + h] + g_ald1[d * H1 + h];
    e = (e > 0.f) ? e : 0.2f * e;
    float p = __expf(e);
    g_p1[idx] = p;
    atomicAdd(&g_s1[d * H1 + h], p);
}

// per-dst aggregation: h1act = elu( rs[h]*sum_e p*h1pre[src] + b1 )
__global__ void agg1_kernel(const float* __restrict__ b1) {
    int node = blockIdx.x;
    int t = threadIdx.x;           // 128
    __shared__ float rs[H1];
    __shared__ int ssrc[128];
    __shared__ int seid[128];
    if (t < H1) rs[t] = 1.0f / (g_s1[node * H1 + t] + 1e-16f);
    int start = g_rowstart[node], d = g_deg[node];
    const int f0 = t, f1 = t + 128, f2 = t + 256;
    const int h0 = f0 / C1, h1 = f1 / C1, h2 = (f2 < D1) ? f2 / C1 : 0;
    float a0 = 0.f, a1 = 0.f, a2 = 0.f;
    for (int base = 0; base < d; base += 128) {
        int m = min(128, d - base);
        __syncthreads();
        if (t < m) {
            int eid = g_order[start + base + t];
            seid[t] = eid;
            ssrc[t] = g_src[eid];
        }
        __syncthreads();
        for (int e = 0; e < m; e++) {
            int eid = seid[e];
            const float* hr = &g_h1pre[(size_t)ssrc[e] * D1];
            const float* pr = &g_p1[(size_t)eid * H1];
            a0 = fmaf(pr[h0], hr[f0], a0);
            a1 = fmaf(pr[h1], hr[f1], a1);
            if (f2 < D1) a2 = fmaf(pr[h2], hr[f2], a2);
        }
    }
    __syncthreads();
    float v0 = a0 * rs[h0] + b1[f0];
    v0 = (v0 > 0.f) ? v0 : (__expf(v0) - 1.f);
    g_h1act[(size_t)node * D1 + f0] = v0;
    float v1 = a1 * rs[h1] + b1[f1];
    v1 = (v1 > 0.f) ? v1 : (__expf(v1) - 1.f);
    g_h1act[(size_t)node * D1 + f1] = v1;
    if (f2 < D1) {
        float v2 = a2 * rs[h2] + b1[f2];
        v2 = (v2 > 0.f) ? v2 : (__expf(v2) - 1.f);
        g_h1act[(size_t)node * D1 + f2] = v2;
    }
}

// ---------------- layer 2 ----------------
__global__ void mm2_kernel(const float* __restrict__ W2) {
    // 16 nodes per block, 128 threads (1 output feature each)
    int n0 = blockIdx.x * 16;
    int t = threadIdx.x;
    __shared__ float xs[16 * D1];   // 23 KB
    for (int i = t; i < 16 * D1; i += 128)
        xs[i] = g_h1act[(size_t)n0 * D1 + i];
    __syncthreads();
    float acc[16];
#pragma unroll
    for (int n = 0; n < 16; n++) acc[n] = 0.f;
    for (int k = 0; k < D1; k += 4) {
        float w0 = W2[(k + 0) * D2 + t];
        float w1 = W2[(k + 1) * D2 + t];
        float w2 = W2[(k + 2) * D2 + t];
        float w3 = W2[(k + 3) * D2 + t];
#pragma unroll
        for (int n = 0; n < 16; n++) {
            float4 xv = *(const float4*)&xs[n * D1 + k];
            acc[n] = fmaf(xv.x, w0, acc[n]);
            acc[n] = fmaf(xv.y, w1, acc[n]);
            acc[n] = fmaf(xv.z, w2, acc[n]);
            acc[n] = fmaf(xv.w, w3, acc[n]);
        }
    }
#pragma unroll
    for (int n = 0; n < 16; n++)
        g_h2pre[(size_t)(n0 + n) * D2 + t] = acc[n];
}

__global__ void al2_kernel(const float* __restrict__ asrc2,
                           const float* __restrict__ adst2) {
    // warp per node
    int n = blockIdx.x * 4 + (threadIdx.x >> 5);
    int lane = threadIdx.x & 31;
    float4 v  = *(const float4*)&g_h2pre[(size_t)n * D2 + lane * 4];
    float4 as = *(const float4*)&asrc2[lane * 4];
    float4 ad = *(const float4*)&adst2[lane * 4];
    float ss = v.x * as.x + v.y * as.y + v.z * as.z + v.w * as.w;
    float sd = v.x * ad.x + v.y * ad.y + v.z * ad.z + v.w * ad.w;
#pragma unroll
    for (int off = 16; off; off >>= 1) {
        ss += __shfl_xor_sync(0xffffffffu, ss, off);
        sd += __shfl_xor_sync(0xffffffffu, sd, off);
    }
    if (lane == 0) { g_als2[n] = ss; g_ald2[n] = sd; }
}

__global__ void e2_kernel() {
    int i = blockIdx.x * blockDim.x + threadIdx.x;
    if (i >= ETOT) return;
    int s = g_src[i], d = g_dst[i];
    float e = g_als2[s] + g_ald2[d];
    e = (e > 0.f) ? e : 0.2f * e;
    float p = __expf(e);
    g_p2[i] = p;
    atomicAdd(&g_s2[d], p);
}

__global__ void agg2_kernel(const float* __restrict__ b2) {
    int node = blockIdx.x;
    int t = threadIdx.x;           // 128, one feature each
    __shared__ float rs;
    __shared__ int ssrc[128];
    __shared__ float sp[128];
    if (t == 0) rs = 1.0f / (g_s2[node] + 1e-16f);
    int start = g_rowstart[node], d = g_deg[node];
    float a = 0.f;
    for (int base = 0; base < d; base += 128) {
        int m = min(128, d - base);
        __syncthreads();
        if (t < m) {
            int eid = g_order[start + base + t];
            ssrc[t] = g_src[eid];
            sp[t]   = g_p2[eid];
        }
        __syncthreads();
        for (int e = 0; e < m; e++)
            a = fmaf(sp[e], g_h2pre[(size_t)ssrc[e] * D2 + t], a);
    }
    __syncthreads();
    float v = a * rs + b2[t];
    g_h2act[(size_t)node * D2 + t] = fmaxf(v, 0.f);   // relu fused
}

// ---------------- pool + FC ----------------
__global__ void pool_kernel(const int* __restrict__ batch) {
    int idx = blockIdx.x * blockDim.x + threadIdx.x;
    if (idx >= NN * D2) return;
    int n = idx >> 7, f = idx & 127;
    int b = batch[n];
    b = min(max(b, 0), NG - 1);
    float v = g_h2act[idx];       // >= 0 (relu), so int-max trick is valid
    atomicMax((int*)&g_pool[b * D2 + f], __float_as_int(v));
}

__global__ void fc_kernel(const float* __restrict__ fcw,
                          const float* __restrict__ fcb,
                          float* __restrict__ out) {
    int gi = blockIdx.x, t = threadIdx.x;
    __shared__ float gs[D2];
    float gv = g_pool[gi * D2 + t];
    if (!(gv >= 0.f)) gv = 0.f;   // -inf / NaN (empty graph) -> 0
    gs[t] = gv;
    __syncthreads();
    float s = 0.f;
    for (int k = 0; k < D2; k++)
        s = fmaf(gs[k], fcw[k * D2 + t], s);
    out[gi * D2 + t] = fmaxf(s + fcb[t], 0.f);
}

// ---------------- launcher ----------------
extern "C" void kernel_launch(void* const* d_in, const int* in_sizes, int n_in,
                              void* d_out, int out_size) {
    const float* x     = (const float*)d_in[0];
    const int*   ei    = (const int*)d_in[1];
    const int*   batch = (const int*)d_in[2];
    const float* W1    = (const float*)d_in[3];
    const float* as1   = (const float*)d_in[4];
    const float* ad1   = (const float*)d_in[5];
    const float* b1    = (const float*)d_in[6];
    const float* W2    = (const float*)d_in[7];
    const float* as2   = (const float*)d_in[8];
    const float* ad2   = (const float*)d_in[9];
    const float* b2    = (const float*)d_in[10];
    const float* fcw   = (const float*)d_in[11];
    const float* fcb   = (const float*)d_in[12];
    float* out = (float*)d_out;

    init_kernel<<<256, 256>>>();
    convert_kernel<<<(ETOT + 255) / 256, 256>>>(ei);
    scan_kernel<<<1, 1024>>>();
    scatter_kernel<<<(ETOT + 255) / 256, 256>>>();

    mm1_kernel<<<NN / 8, 384>>>(x, W1, as1, ad1);
    e1_kernel<<<(ETOT * H1 + 255) / 256, 256>>>();
    agg1_kernel<<<NN, 128>>>(b1);

    mm2_kernel<<<NN / 16, 128>>>(W2);
    al2_kernel<<<NN / 4, 128>>>(as2, ad2);
    e2_kernel<<<(ETOT + 255) / 256, 256>>>();
    agg2_kernel<<<NN, 128>>>(b2);

    pool_kernel<<<(NN * D2 + 255) / 256, 256>>>(batch);
    fc_kernel<<<NG, D2>>>(fcw, fcb, out);
}

// round 3
// speedup vs baseline: 1.3185x; 1.3185x over previous
#include <cuda_runtime.h>
#include <math.h>

#define NN    50000
#define NE    800000
#define ETOT  850000     // NE + NN self loops
#define H1    10
#define C1    36
#define D1    360        // H1*C1
#define ALP   12         // padded stride for als1/ald1 rows
#define D2    128
#define NG    128

typedef unsigned long long u64;

__device__ __forceinline__ u64 pack2(float a, float b) {
    u64 r; asm("mov.b64 %0, {%1, %2};" : "=l"(r) : "f"(a), "f"(b)); return r;
}
__device__ __forceinline__ u64 ffma2(u64 a, u64 b, u64 c) {
    u64 d; asm("fma.rn.f32x2 %0, %1, %2, %3;" : "=l"(d) : "l"(a), "l"(b), "l"(c)); return d;
}
__device__ __forceinline__ float2 unpack2(u64 v) {
    float2 r; asm("mov.b64 {%0, %1}, %2;" : "=f"(r.x), "=f"(r.y) : "l"(v)); return r;
}

// ---------------- device scratch ----------------
__device__ int   g_src[ETOT];
__device__ int   g_dst[ETOT];
__device__ int   g_deg[NN];
__device__ int   g_rowstart[NN];
__device__ int   g_cursor[NN];
__device__ int   g_bsum[64];
__device__ int   g_ssrc[ETOT];          // src ids in CSR-by-dst order

__device__ float g_h1pre[(size_t)NN * D1];     // 72 MB
__device__ float g_als1[NN * ALP];
__device__ float g_ald1[NN * ALP];
__device__ float g_h1act[(size_t)NN * D1];     // 72 MB
__device__ float g_h2pre[(size_t)NN * D2];     // 25.6 MB
__device__ float g_als2[NN];
__device__ float g_ald2[NN];
__device__ float g_h2act[(size_t)NN * D2];     // 25.6 MB
__device__ float g_pool[NG * D2];

// ---------------- init / CSR build ----------------
__global__ void init_kernel() {
    int i = blockIdx.x * blockDim.x + threadIdx.x;
    int stride = gridDim.x * blockDim.x;
    for (int j = i; j < NN; j += stride) { g_deg[j] = 0; g_cursor[j] = 0; }
    for (int j = i; j < NG * D2; j += stride)
        g_pool[j] = __int_as_float(0xFF800000); // -inf
}

__global__ void convert_kernel(const int* __restrict__ ei) {
    int i = blockIdx.x * blockDim.x + threadIdx.x;
    if (i >= ETOT) return;
    int s, d;
    if (i < NE) {
        s = ei[i]; d = ei[NE + i];
        s = min(max(s, 0), NN - 1);
        d = min(max(d, 0), NN - 1);
    } else {
        s = d = i - NE;                      // self loop
    }
    g_src[i] = s; g_dst[i] = d;
    atomicAdd(&g_deg[d], 1);
}

__global__ void scanA_kernel() {
    __shared__ int tmp[1024];
    int b = blockIdx.x, t = threadIdx.x;
    int i = b * 1024 + t;
    int v = (i < NN) ? g_deg[i] : 0;
    tmp[t] = v;
    __syncthreads();
    for (int off = 1; off < 1024; off <<= 1) {
        int add = (t >= off) ? tmp[t - off] : 0;
        __syncthreads();
        tmp[t] += add;
        __syncthreads();
    }
    if (i < NN) g_rowstart[i] = tmp[t] - v;     // exclusive (local)
    if (t == 1023) g_bsum[b] = tmp[1023];
}

__global__ void scanB_kernel() {
    __shared__ int tmp[64];
    int t = threadIdx.x;
    int v = (t < 49) ? g_bsum[t] : 0;
    tmp[t] = v;
    __syncthreads();
    for (int off = 1; off < 64; off <<= 1) {
        int add = (t >= off) ? tmp[t - off] : 0;
        __syncthreads();
        tmp[t] += add;
        __syncthreads();
    }
    if (t < 49) g_bsum[t] = tmp[t] - v;         // exclusive
}

__global__ void scanC_kernel() {
    int i = blockIdx.x * blockDim.x + threadIdx.x;
    if (i < NN) g_rowstart[i] += g_bsum[i >> 10];
}

__global__ void scatter_kernel() {
    int i = blockIdx.x * blockDim.x + threadIdx.x;
    if (i >= ETOT) return;
    int d = g_dst[i];
    int pos = g_rowstart[d] + atomicAdd(&g_cursor[d], 1);
    g_ssrc[pos] = g_src[i];
}

// ---------------- layer 1: h1 = x@W1, attention coefficients ----------------
__global__ void mm1_kernel(const float* __restrict__ x,
                           const float* __restrict__ W1,
                           const float* __restrict__ asrc,
                           const float* __restrict__ adst) {
    // 8 nodes per block, 384 threads (360 active)
    int n0 = blockIdx.x * 8;
    int t = threadIdx.x;
    __shared__ float xs[8 * C1];
    __shared__ float hs[8 * D1];
    if (t < 8 * C1) xs[t] = x[(size_t)n0 * C1 + t];
    __syncthreads();
    if (t < D1) {
        float acc[8];
#pragma unroll
        for (int n = 0; n < 8; n++) acc[n] = 0.f;
        for (int k = 0; k < C1; k++) {
            float w = W1[k * D1 + t];
#pragma unroll
            for (int n = 0; n < 8; n++) acc[n] = fmaf(xs[n * C1 + k], w, acc[n]);
        }
#pragma unroll
        for (int n = 0; n < 8; n++) {
            g_h1pre[(size_t)(n0 + n) * D1 + t] = acc[n];
            hs[n * D1 + t] = acc[n];
        }
    }
    __syncthreads();
    if (t < 160) {   // 8 nodes * 10 heads * {src,dst}
        int n = t / 20, r = t % 20, h = r >> 1, sd = r & 1;
        const float* a = sd ? adst : asrc;
        float s = 0.f;
        for (int c = 0; c < C1; c++)
            s = fmaf(hs[n * D1 + h * C1 + c], a[h * C1 + c], s);
        if (sd) g_ald1[(n0 + n) * ALP + h] = s;
        else    g_als1[(n0 + n) * ALP + h] = s;
    }
}

// layer-1 aggregation with inline softmax (p computed in-kernel, no atomics)
__global__ void agg1_kernel(const float* __restrict__ b1) {
    int node = blockIdx.x;
    int t = threadIdx.x;            // 128
    __shared__ int   ssrcs[128];
    __shared__ float sp[128 * H1];  // 5 KB
    __shared__ float aldn[H1];
    __shared__ float ssum[H1];
    if (t < H1) aldn[t] = g_ald1[node * ALP + t];

    int start = g_rowstart[node], deg = g_deg[node];
    const int head = (t < 90) ? (t / 9) : 0;
    u64 acc01 = 0, acc23 = 0;       // packed f32x2 accumulators (zeros)
    float hsum = 0.f;

    for (int base = 0; base < deg; base += 128) {
        int m = min(128, deg - base);
        __syncthreads();
        if (t < m) {
            int s = g_ssrc[start + base + t];
            ssrcs[t] = s;
            const float* ar = &g_als1[(size_t)s * ALP];
            float4 a0 = *(const float4*)ar;
            float4 a1 = *(const float4*)(ar + 4);
            float2 a2 = *(const float2*)(ar + 8);
            float e;
#define DOH(val, h) e = (val) + aldn[h]; e = (e > 0.f) ? e : 0.2f * e; sp[t * H1 + (h)] = __expf(e);
            DOH(a0.x, 0) DOH(a0.y, 1) DOH(a0.z, 2) DOH(a0.w, 3)
            DOH(a1.x, 4) DOH(a1.y, 5) DOH(a1.z, 6) DOH(a1.w, 7)
            DOH(a2.x, 8) DOH(a2.y, 9)
#undef DOH
        }
        __syncthreads();
        if (t < 90) {
            for (int e = 0; e < m; e++) {
                int s = ssrcs[e];
                float p = sp[e * H1 + head];
                u64 pf2 = pack2(p, p);
                const ulonglong2* hp =
                    (const ulonglong2*)(g_h1pre + (size_t)s * D1 + 4 * t);
                ulonglong2 hv = *hp;
                acc01 = ffma2(hv.x, pf2, acc01);
                acc23 = ffma2(hv.y, pf2, acc23);
            }
        } else if (t >= 90 && t < 100) {
            int h = t - 90;
            for (int e = 0; e < m; e++) hsum += sp[e * H1 + h];
        }
    }
    if (t >= 90 && t < 100) ssum[t - 90] = hsum;
    __syncthreads();
    if (t < 90) {
        float rs = 1.0f / (ssum[head] + 1e-16f);
        float2 v01 = unpack2(acc01);
        float2 v23 = unpack2(acc23);
        float4 bv = *(const float4*)(b1 + 4 * t);
        float4 o;
        o.x = v01.x * rs + bv.x;
        o.y = v01.y * rs + bv.y;
        o.z = v23.x * rs + bv.z;
        o.w = v23.y * rs + bv.w;
        o.x = (o.x > 0.f) ? o.x : (__expf(o.x) - 1.f);
        o.y = (o.y > 0.f) ? o.y : (__expf(o.y) - 1.f);
        o.z = (o.z > 0.f) ? o.z : (__expf(o.z) - 1.f);
        o.w = (o.w > 0.f) ? o.w : (__expf(o.w) - 1.f);
        *(float4*)(g_h1act + (size_t)node * D1 + 4 * t) = o;
    }
}

// ---------------- layer 2 ----------------
// h2pre = h1act @ W2, 32 nodes/block, FFMA2 with node-pair packing
#define MM2_N 32
#define MM2_STRIDE 36   // padded node stride in transposed smem (16B-aligned rows)
__global__ void mm2_kernel(const float* __restrict__ W2) {
    extern __shared__ float xs[];            // [D1][MM2_STRIDE] = 51840 B
    int n0 = blockIdx.x * MM2_N;
    int t = threadIdx.x;                     // 128
    for (int i = t; i < MM2_N * D1; i += 128) {
        int n = i / D1, k = i % D1;
        float v = (n0 + n < NN) ? g_h1act[(size_t)(n0 + n) * D1 + k] : 0.f;
        xs[k * MM2_STRIDE + n] = v;
    }
    __syncthreads();
    u64 acc[MM2_N / 2];
#pragma unroll
    for (int p = 0; p < MM2_N / 2; p++) acc[p] = 0;
    for (int k = 0; k < D1; k++) {
        float w = W2[k * D2 + t];
        u64 wf2 = pack2(w, w);
        const ulonglong2* row = (const ulonglong2*)(xs + k * MM2_STRIDE);
#pragma unroll
        for (int q = 0; q < MM2_N / 4; q++) {
            ulonglong2 v = row[q];
            acc[2 * q]     = ffma2(v.x, wf2, acc[2 * q]);
            acc[2 * q + 1] = ffma2(v.y, wf2, acc[2 * q + 1]);
        }
    }
#pragma unroll
    for (int p = 0; p < MM2_N / 2; p++) {
        float2 a = unpack2(acc[p]);
        int n = n0 + 2 * p;
        if (n < NN)     g_h2pre[(size_t)n * D2 + t] = a.x;
        if (n + 1 < NN) g_h2pre[(size_t)(n + 1) * D2 + t] = a.y;
    }
}

__global__ void al2_kernel(const float* __restrict__ asrc2,
                           const float* __restrict__ adst2) {
    int n = blockIdx.x * 4 + (threadIdx.x >> 5);
    int lane = threadIdx.x & 31;
    float4 v  = *(const float4*)&g_h2pre[(size_t)n * D2 + lane * 4];
    float4 as = *(const float4*)&asrc2[lane * 4];
    float4 ad = *(const float4*)&adst2[lane * 4];
    float ss = v.x * as.x + v.y * as.y + v.z * as.z + v.w * as.w;
    float sd = v.x * ad.x + v.y * ad.y + v.z * ad.z + v.w * ad.w;
#pragma unroll
    for (int off = 16; off; off >>= 1) {
        ss += __shfl_xor_sync(0xffffffffu, ss, off);
        sd += __shfl_xor_sync(0xffffffffu, sd, off);
    }
    if (lane == 0) { g_als2[n] = ss; g_ald2[n] = sd; }
}

// layer-2 aggregation: warp per node, inline softmax, shuffle-staged edges
__global__ void agg2_kernel(const float* __restrict__ b2) {
    int node = blockIdx.x * 4 + (threadIdx.x >> 5);
    int lane = threadIdx.x & 31;
    float aldn = g_ald2[node];
    int start = g_rowstart[node], deg = g_deg[node];
    u64 acc01 = 0, acc23 = 0;
    float psum = 0.f;
    for (int base = 0; base < deg; base += 32) {
        int m = min(32, deg - base);
        int s = 0; float p = 0.f;
        if (lane < m) {
            s = g_ssrc[start + base + lane];
            float e = g_als2[s] + aldn;
            e = (e > 0.f) ? e : 0.2f * e;
            p = __expf(e);
        }
        psum += p;
        for (int j = 0; j < m; j++) {
            int ss = __shfl_sync(0xffffffffu, s, j);
            float pp = __shfl_sync(0xffffffffu, p, j);
            u64 pf2 = pack2(pp, pp);
            const ulonglong2* hp =
                (const ulonglong2*)(g_h2pre + (size_t)ss * D2 + 4 * lane);
            ulonglong2 hv = *hp;
            acc01 = ffma2(hv.x, pf2, acc01);
            acc23 = ffma2(hv.y, pf2, acc23);
        }
    }
#pragma unroll
    for (int off = 16; off; off >>= 1)
        psum += __shfl_xor_sync(0xffffffffu, psum, off);
    float rs = 1.0f / (psum + 1e-16f);
    float2 v01 = unpack2(acc01);
    float2 v23 = unpack2(acc23);
    float4 bv = *(const float4*)(b2 + 4 * lane);
    float4 o;
    o.x = fmaxf(v01.x * rs + bv.x, 0.f);
    o.y = fmaxf(v01.y * rs + bv.y, 0.f);
    o.z = fmaxf(v23.x * rs + bv.z, 0.f);
    o.w = fmaxf(v23.y * rs + bv.w, 0.f);
    *(float4*)(g_h2act + (size_t)node * D2 + 4 * lane) = o;
}

// ---------------- pool + FC ----------------
// batch is sorted -> per-block register max over contiguous node range
__global__ void pool_kernel(const int* __restrict__ batch) {
    int t = threadIdx.x;                   // 128 = feature
    int n0 = blockIdx.x * 256;
    int n1 = min(n0 + 256, NN);
    float cur = __int_as_float(0xFF800000);
    int curb = min(max(batch[n0], 0), NG - 1);
    for (int n = n0; n < n1; n++) {
        int b = min(max(batch[n], 0), NG - 1);
        if (b != curb) {
            atomicMax((int*)&g_pool[curb * D2 + t], __float_as_int(cur));
            cur = __int_as_float(0xFF800000);
            curb = b;
        }
        cur = fmaxf(cur, g_h2act[(size_t)n * D2 + t]);
    }
    atomicMax((int*)&g_pool[curb * D2 + t], __float_as_int(cur));
}

__global__ void fc_kernel(const float* __restrict__ fcw,
                          const float* __restrict__ fcb,
                          float* __restrict__ out) {
    int gi = blockIdx.x, t = threadIdx.x;
    __shared__ float gs[D2];
    float gv = g_pool[gi * D2 + t];
    if (!(gv >= 0.f)) gv = 0.f;   // -inf (empty graph) -> 0
    gs[t] = gv;
    __syncthreads();
    float s = 0.f;
    for (int k = 0; k < D2; k++)
        s = fmaf(gs[k], fcw[k * D2 + t], s);
    out[gi * D2 + t] = fmaxf(s + fcb[t], 0.f);
}

// ---------------- launcher ----------------
extern "C" void kernel_launch(void* const* d_in, const int* in_sizes, int n_in,
                              void* d_out, int out_size) {
    const float* x     = (const float*)d_in[0];
    const int*   ei    = (const int*)d_in[1];
    const int*   batch = (const int*)d_in[2];
    const float* W1    = (const float*)d_in[3];
    const float* as1   = (const float*)d_in[4];
    const float* ad1   = (const float*)d_in[5];
    const float* b1    = (const float*)d_in[6];
    const float* W2    = (const float*)d_in[7];
    const float* as2   = (const float*)d_in[8];
    const float* ad2   = (const float*)d_in[9];
    const float* b2    = (const float*)d_in[10];
    const float* fcw   = (const float*)d_in[11];
    const float* fcb   = (const float*)d_in[12];
    float* out = (float*)d_out;

    static bool attr_set = false;
    if (!attr_set) {
        cudaFuncSetAttribute(mm2_kernel,
                             cudaFuncAttributeMaxDynamicSharedMemorySize,
                             D1 * MM2_STRIDE * 4);
        attr_set = true;
    }

    init_kernel<<<128, 256>>>();
    convert_kernel<<<(ETOT + 255) / 256, 256>>>(ei);
    scanA_kernel<<<49, 1024>>>();
    scanB_kernel<<<1, 64>>>();
    scanC_kernel<<<49, 1024>>>();
    scatter_kernel<<<(ETOT + 255) / 256, 256>>>();

    mm1_kernel<<<NN / 8, 384>>>(x, W1, as1, ad1);
    agg1_kernel<<<NN, 128>>>(b1);

    mm2_kernel<<<(NN + MM2_N - 1) / MM2_N, 128, D1 * MM2_STRIDE * 4>>>(W2);
    al2_kernel<<<NN / 4, 128>>>(as2, ad2);
    agg2_kernel<<<NN / 4, 128>>>(b2);

    pool_kernel<<<(NN + 255) / 256, 128>>>(batch);
    fc_kernel<<<NG, D2>>>(fcw, fcb, out);
}